// round 14
// baseline (speedup 1.0000x reference)
#include <cuda_runtime.h>
#include <cstdint>

#define Bz 128
#define Sz 64
#define Ez 300
#define Hz 512
#define Lz 5
#define GXW 1536   // 3*H : i, f, u x-side preactivations
#define NBLK 128
#define NTHR 512

// ---- device scratch (no allocation allowed) --------------------------------
__device__ float g_Gx  [(size_t)Bz * Sz * GXW];
__device__ float g_allH[(size_t)Bz * Sz * Hz];
__device__ float g_allC[(size_t)Bz * Sz * Hz];
__device__ float g_WfhH[(size_t)Bz * Sz * Hz];    // cache: Wfh @ allH[b,s]
__device__ float g_hsum[Bz * Hz];
__device__ float g_hprev[Bz * Hz];
__device__ float g_y[Bz * 4 * Hz];                // [b][{yi,yo,yu,y4}][h]
__device__ unsigned int g_bar_count;
__device__ unsigned int g_bar_gen;

// ---- f32x2 packed FMA helpers ----------------------------------------------
static __device__ __forceinline__ unsigned long long pk2(float x, float y) {
    unsigned long long r;
    asm("mov.b64 %0, {%1, %2};" : "=l"(r) : "f"(x), "f"(y));
    return r;
}
static __device__ __forceinline__ unsigned long long fma2(unsigned long long a,
                                                          unsigned long long b,
                                                          unsigned long long c) {
    unsigned long long d;
    asm("fma.rn.f32x2 %0, %1, %2, %3;" : "=l"(d) : "l"(a), "l"(b), "l"(c));
    return d;
}
static __device__ __forceinline__ float2 upk2(unsigned long long v) {
    float lo, hi;
    asm("mov.b64 {%0, %1}, %2;" : "=f"(lo), "=f"(hi) : "l"(v));
    return make_float2(lo, hi);
}
static __device__ __forceinline__ float sigm(float z) {
    return 1.0f / (1.0f + expf(-z));
}
static __device__ __forceinline__ float ldcg1(const float* p) {
    float v;
    asm volatile("ld.global.cg.f32 %0, [%1];" : "=f"(v) : "l"(p));
    return v;
}
static __device__ __forceinline__ float4 ldcg4(const float* p) {
    float4 v;
    asm volatile("ld.global.cg.v4.f32 {%0,%1,%2,%3}, [%4];"
                 : "=f"(v.x), "=f"(v.y), "=f"(v.z), "=f"(v.w) : "l"(p));
    return v;
}

// ---- P0: zero recurrent state + barrier vars -------------------------------
__global__ void k_init() {
    const size_t n = (size_t)Bz * Sz * Hz;
    const size_t stride = (size_t)gridDim.x * blockDim.x;
    size_t i = (size_t)blockIdx.x * blockDim.x + threadIdx.x;
    for (size_t j = i; j < n; j += stride) {
        g_allH[j] = 0.f; g_allC[j] = 0.f; g_WfhH[j] = 0.f;
    }
    for (size_t j = i; j < (size_t)Bz * Hz; j += stride) {
        g_hsum[j] = 0.f; g_hprev[j] = 0.f;
    }
    if (i == 0) { g_bar_count = 0u; g_bar_gen = 0u; }
}

// ---- P1: Gx = embed[x] @ {Wix,Wfx,Wux}^T + bias (known-good) ---------------
__global__ __launch_bounds__(256) void k_precompute(
    const int* __restrict__ x, const float* __restrict__ embed,
    const float* __restrict__ Wix, const float* __restrict__ bix,
    const float* __restrict__ Wfx, const float* __restrict__ bfx,
    const float* __restrict__ Wux, const float* __restrict__ bux)
{
    const int nt = blockIdx.x;            // 0..23
    const int mt = blockIdx.y;            // 0..127
    const int g  = nt >> 3;
    const int jbase = (nt & 7) * 64;
    const float* W    = (g == 0) ? Wix : (g == 1) ? Wfx : Wux;
    const float* bias = (g == 0) ? bix : (g == 1) ? bfx : bux;
    const int tid = threadIdx.x;

    __shared__ int wid[64];
    __shared__ __align__(16) float As[16][64];
    __shared__ __align__(16) float Bs[16][64];

    const int rowbase = mt * 64;
    if (tid < 64) wid[tid] = x[rowbase + tid];
    __syncthreads();

    const int sm  = tid >> 2;
    const int skq = tid & 3;
    const int tm  = tid >> 4;
    const int tn  = tid & 15;

    unsigned long long acc[4][2];
#pragma unroll
    for (int r = 0; r < 4; r++) { acc[r][0] = 0ull; acc[r][1] = 0ull; }

    for (int kc = 0; kc < 19; kc++) {
        const int k = kc * 16 + skq * 4;
        float4 va = make_float4(0.f,0.f,0.f,0.f), vb = va;
        if (k < Ez) {
            va = *reinterpret_cast<const float4*>(&embed[(size_t)wid[sm] * Ez + k]);
            vb = *reinterpret_cast<const float4*>(&W[(size_t)(jbase + sm) * Ez + k]);
        }
        As[skq*4+0][sm]=va.x; As[skq*4+1][sm]=va.y; As[skq*4+2][sm]=va.z; As[skq*4+3][sm]=va.w;
        Bs[skq*4+0][sm]=vb.x; Bs[skq*4+1][sm]=vb.y; Bs[skq*4+2][sm]=vb.z; Bs[skq*4+3][sm]=vb.w;
        __syncthreads();
#pragma unroll
        for (int kk = 0; kk < 16; kk++) {
            const float4 a4 = *reinterpret_cast<const float4*>(&As[kk][tm * 4]);
            const ulonglong2 bv = *reinterpret_cast<const ulonglong2*>(&Bs[kk][tn * 4]);
            const unsigned long long a0 = pk2(a4.x, a4.x);
            const unsigned long long a1 = pk2(a4.y, a4.y);
            const unsigned long long a2 = pk2(a4.z, a4.z);
            const unsigned long long a3 = pk2(a4.w, a4.w);
            acc[0][0]=fma2(a0,bv.x,acc[0][0]); acc[0][1]=fma2(a0,bv.y,acc[0][1]);
            acc[1][0]=fma2(a1,bv.x,acc[1][0]); acc[1][1]=fma2(a1,bv.y,acc[1][1]);
            acc[2][0]=fma2(a2,bv.x,acc[2][0]); acc[2][1]=fma2(a2,bv.y,acc[2][1]);
            acc[3][0]=fma2(a3,bv.x,acc[3][0]); acc[3][1]=fma2(a3,bv.y,acc[3][1]);
        }
        __syncthreads();
    }

    const int j = jbase + tn * 4;
#pragma unroll
    for (int r = 0; r < 4; r++) {
        const int row = rowbase + tm * 4 + r;
        float* dst = &g_Gx[(size_t)row * GXW + g * Hz + j];
        const float2 p0 = upk2(acc[r][0]);
        const float2 p1 = upk2(acc[r][1]);
        dst[0] = p0.x + bias[j+0]; dst[1] = p0.y + bias[j+1];
        dst[2] = p1.x + bias[j+2]; dst[3] = p1.y + bias[j+3];
    }
}

// ---- grid-wide sense barrier (R9-proven atomic version + backoff) ----------
static __device__ __forceinline__ void gridbar(unsigned int& gen) {
    __syncthreads();
    if (threadIdx.x == 0) {
        __threadfence();
        unsigned int a = atomicAdd(&g_bar_count, 1u);
        if (a == NBLK - 1) {
            g_bar_count = 0u;
            __threadfence();
            atomicExch(&g_bar_gen, gen + 1u);
        } else {
            while (atomicAdd(&g_bar_gen, 0u) <= gen) { __nanosleep(64); }
        }
        __threadfence();
    }
    gen++;
    __syncthreads();
}

// ---- persistent recurrence kernel ------------------------------------------
// smem: Wp 512x32 u64 (128KB) | As 2x64x64 f (32KB) | lists (8KB) | small
#define SM_WP    0
#define SM_AS    131072
#define SM_L0    163840            // short[64*64] = 8KB
#define SM_CNT   172032            // int[64]
#define SM_BFS   172288            // int[64]
#define SM_PM    172544            // u64[64]
#define SMEM_TOTAL 173568

extern __shared__ unsigned char smem_raw[];

__global__ __launch_bounds__(NTHR, 1) void k_recur(
    const int* __restrict__ bfs, const int* __restrict__ children,
    const float* __restrict__ Wih, const float* __restrict__ Wfh,
    const float* __restrict__ Wuh,
    const float* __restrict__ bih, const float* __restrict__ bfh,
    const float* __restrict__ buh,
    const float* __restrict__ Wout, const float* __restrict__ bout,
    float* __restrict__ out)
{
    const int blk = blockIdx.x;
    const int tid = threadIdx.x;

    unsigned long long* Wp = (unsigned long long*)(smem_raw + SM_WP);
    float* As   = (float*)(smem_raw + SM_AS);
    short* s_l0 = (short*)(smem_raw + SM_L0);
    int*   s_cnt = (int*)(smem_raw + SM_CNT);
    int*   s_bfs = (int*)(smem_raw + SM_BFS);
    unsigned long long* s_pm = (unsigned long long*)(smem_raw + SM_PM);

    // GEMM tile assignment
    const int mt = blk >> 6;             // rows [mt*64, +64)  (batches)
    const int nt = blk & 63;             // cols [nt*32, +32)
    const int colbase = nt * 32;
    const int g = colbase >> 9;          // gate 0..3
    const int wrow0 = colbase & 511;
    const float* Wsrc = (g == 0) ? Wih : (g == 2) ? Wuh : Wfh;
    const int m0row = mt * 64;

    // one-time: W tile into smem as (w,w) pairs
    for (int i = tid; i < 32 * 512; i += NTHR) {
        const int c = i & 31, k = i >> 5;
        const float w = Wsrc[(size_t)(wrow0 + c) * Hz + k];
        Wp[(size_t)k * 32 + c] = pk2(w, w);
    }
    if (tid < Sz) s_bfs[tid] = bfs[blk * Sz + tid];
    const float vbih = bih[tid], vbfh = bfh[tid], vbuh = buh[tid];
    __syncthreads();

    // procmask prefix (serial, once)
    if (tid == 0) {
        unsigned long long pm = 0ull;
        for (int t = 0; t < Sz; t++) { s_pm[t] = pm; pm |= 1ull << s_bfs[t]; }
    }
    __syncthreads();

    const int wz = tid >> 5, lane = tid & 31;

    // build per-step child lists via ballot compaction (once)
    for (int q = 0; q < 4; q++) {
        const int t = wz + q * 16;
        const int cu = s_bfs[t];
        const unsigned long long pm = s_pm[t];
        const int* chrow = &children[((size_t)blk * Sz + cu) * Sz];
        const int s0 = lane, s1 = lane + 32;
        const bool p0 = (chrow[s0] != 0) && ((pm >> s0) & 1ull);
        const bool p1 = (chrow[s1] != 0) && ((pm >> s1) & 1ull);
        const unsigned b0 = __ballot_sync(0xffffffffu, p0);
        const unsigned b1 = __ballot_sync(0xffffffffu, p1);
        const unsigned mlt = (1u << lane) - 1u;
        if (p0) s_l0[t * 64 + __popc(b0 & mlt)] = (short)s0;
        if (p1) s_l0[t * 64 + __popc(b0) + __popc(b1 & mlt)] = (short)s1;
        if (lane == 0) s_cnt[t] = __popc(b0) + __popc(b1);
    }
    __syncthreads();

    // compute-warp geometry (warps 0..7): thread = 2 rows x 4 cols
    const int wr = (wz >> 1) & 3, wc = wz & 1;
    const int lr = lane >> 2,     lc = lane & 3;
    const int rloc = wr * 16 + lr * 2;               // even row in [0,64)
    const int cloc = wc * 16 + lc * 4;               // col in [0,32)
    const int h = tid;
    const size_t bh = (size_t)blk * Sz * Hz + h;

    unsigned int gen = 0;

    for (int t = 0; t < Sz; t++) {
        // ===================== GEMM: y = A @ Wtile^T =====================
        const float* Asrc = (g == 3) ? g_hprev : g_hsum;

        for (int i = tid; i < 1024; i += NTHR) {      // stage chunk 0
            const int row = i >> 4, kq = i & 15;
            const float4 v = ldcg4(&Asrc[(size_t)(m0row + row) * Hz + kq * 4]);
            const int rS = row ^ (kq << 2);
            float* d = &As[(kq * 4) * 64 + rS];
            d[0] = v.x; d[64] = v.y; d[128] = v.z; d[192] = v.w;
        }
        __syncthreads();

        unsigned long long acc0 = 0, acc1 = 0, acc2 = 0, acc3 = 0;
        for (int kc = 0; kc < 8; kc++) {
            const int cb = kc & 1;
            if (wz >= 8) {                            // staging warps
                if (kc < 7) {
                    const int nb = (cb ^ 1) * 4096;
                    for (int i = tid - 256; i < 1024; i += 256) {
                        const int row = i >> 4, kq = i & 15;
                        const float4 v = ldcg4(
                            &Asrc[(size_t)(m0row + row) * Hz + (kc + 1) * 64 + kq * 4]);
                        const int rS = row ^ (kq << 2);
                        float* d = &As[nb + (kq * 4) * 64 + rS];
                        d[0] = v.x; d[64] = v.y; d[128] = v.z; d[192] = v.w;
                    }
                }
            } else {                                  // compute warps (2/SMSP)
                const float* Ab = &As[cb * 4096];
                const unsigned long long* Wb = &Wp[(size_t)(kc * 64) * 32];
#pragma unroll
                for (int kk = 0; kk < 64; kk++) {
                    const int v = ((kk >> 2) & 15) << 2;
                    const unsigned long long ar =
                        *reinterpret_cast<const unsigned long long*>(
                            &Ab[kk * 64 + (rloc ^ v)]);
                    const ulonglong2 w01 = *reinterpret_cast<const ulonglong2*>(
                        &Wb[kk * 32 + cloc]);
                    const ulonglong2 w23 = *reinterpret_cast<const ulonglong2*>(
                        &Wb[kk * 32 + cloc + 2]);
                    acc0 = fma2(ar, w01.x, acc0);
                    acc1 = fma2(ar, w01.y, acc1);
                    acc2 = fma2(ar, w23.x, acc2);
                    acc3 = fma2(ar, w23.y, acc3);
                }
            }
            __syncthreads();
        }

        if (wz < 8) {                                 // epilogue: 2x STG.128
            const int grow = m0row + rloc;
            const int gcol = colbase + cloc;
            const float2 c0 = upk2(acc0), c1 = upk2(acc1);
            const float2 c2 = upk2(acc2), c3 = upk2(acc3);
            *reinterpret_cast<float4*>(&g_y[(size_t)grow * 2048 + gcol]) =
                make_float4(c0.x, c1.x, c2.x, c3.x);
            *reinterpret_cast<float4*>(&g_y[(size_t)(grow + 1) * 2048 + gcol]) =
                make_float4(c0.y, c1.y, c2.y, c3.y);
        }

        // ============ batch-local gathers (pre-barrier overlap) ============
        const int cu = s_bfs[t];
        const int pv = (t > 0)      ? s_bfs[t - 1] : -1;
        const int nx = (t < Sz - 1) ? s_bfs[t + 1] : -1;
        const int n0 = s_cnt[t];
        const int n1 = (t < Sz - 1) ? s_cnt[t + 1] : 0;
        const short* L0 = &s_l0[t * 64];
        const short* L1 = &s_l0[(t + 1) * 64];

        const float* gx = &g_Gx[(size_t)(blk * Sz + cu) * GXW];
        const float gxi = gx[h], gxf = gx[Hz + h], gxu = gx[2 * Hz + h];
        const float base = gxf + vbfh;
        const float Cprev = (pv >= 0) ? g_allC[bh + (size_t)pv * Hz] : 0.f;

        float fc = 0.f, hs = 0.f;
        int fcPrev = 0, hsCur = 0;
        const int nm = (n0 > n1) ? n0 : n1;
#pragma unroll 2
        for (int i = 0; i < nm; i++) {
            if (i < n0) {
                const int s = L0[i];
                if (s != pv)
                    fc += sigm(g_WfhH[bh + (size_t)s * Hz] + base) *
                          g_allC[bh + (size_t)s * Hz];
                else fcPrev = 1;
            }
            if (i < n1) {
                const int s = L1[i];
                if (s != cu) hs += g_allH[bh + (size_t)s * Hz];
                else hsCur = 1;
            }
        }

        gridbar(gen);   // barrier A: all y tiles visible

        // ============ post-barrier finish (tiny) ============
        const float* yb = &g_y[(size_t)blk * 2048];
        const float yi = ldcg1(yb + h);
        const float yo = ldcg1(yb + Hz + h);
        const float yu = ldcg1(yb + 2 * Hz + h);
        const float y4 = ldcg1(yb + 3 * Hz + h);

        const float ig = sigm(gxi + yi + vbih);
        const float og = sigm(gxf + yo + vbfh);   // faithful: 'o' uses fx/fh
        const float ug = tanhf(gxu + yu + vbuh);
        if (fcPrev) fc += sigm(y4 + base) * Cprev;
        const float cc = ig * ug + fc;
        const float hn = og * tanhf(cc);
        if (hsCur) hs += hn;

        g_allC[bh + (size_t)cu * Hz] = cc;
        g_allH[bh + (size_t)cu * Hz] = hn;
        if (pv >= 0) g_WfhH[bh + (size_t)pv * Hz] = y4;
        g_hprev[blk * Hz + h] = hn;
        if (nx >= 0) g_hsum[blk * Hz + h] = hs;

        gridbar(gen);   // barrier B: hsum/hprev visible for next GEMM
    }

    // ===================== output head =====================
    if (tid < 32 * Lz) {
        const int w = tid >> 5, ln = tid & 31;
        float p = 0.f;
        for (int hh = ln; hh < Hz; hh += 32)
            p += g_hprev[blk * Hz + hh] * Wout[w * Hz + hh];
#pragma unroll
        for (int o = 16; o; o >>= 1) p += __shfl_down_sync(0xffffffffu, p, o);
        if (ln == 0) out[blk * Lz + w] = p + bout[w];
    }
}

// ---- launch ----------------------------------------------------------------
extern "C" void kernel_launch(void* const* d_in, const int* in_sizes, int n_in,
                              void* d_out, int out_size) {
    const int*   x        = (const int*)d_in[0];
    const int*   bfs      = (const int*)d_in[1];
    const int*   children = (const int*)d_in[2];
    const float* embed    = (const float*)d_in[3];
    const float* Wix = (const float*)d_in[4],  *bix = (const float*)d_in[5];
    const float* Wih = (const float*)d_in[6],  *bih = (const float*)d_in[7];
    const float* Wfx = (const float*)d_in[8],  *bfx = (const float*)d_in[9];
    const float* Wfh = (const float*)d_in[10], *bfh = (const float*)d_in[11];
    const float* Wux = (const float*)d_in[12], *bux = (const float*)d_in[13];
    const float* Wuh = (const float*)d_in[14], *buh = (const float*)d_in[15];
    const float* Wout = (const float*)d_in[16], *bout = (const float*)d_in[17];
    float* out = (float*)d_out;

    static bool attr_set = false;
    if (!attr_set) {
        cudaFuncSetAttribute(k_recur, cudaFuncAttributeMaxDynamicSharedMemorySize,
                             SMEM_TOTAL);
        attr_set = true;
    }

    k_init<<<1024, 256>>>();
    k_precompute<<<dim3(24, 128), 256>>>(x, embed, Wix, bix, Wfx, bfx, Wux, bux);
    k_recur<<<NBLK, NTHR, SMEM_TOTAL>>>(bfs, children, Wih, Wfh, Wuh,
                                        bih, bfh, buh, Wout, bout, out);
}

// round 16
// speedup vs baseline: 1.1705x; 1.1705x over previous
#include <cuda_runtime.h>
#include <cstdint>

#define Bz 128
#define Sz 64
#define Ez 300
#define Hz 512
#define Lz 5
#define GXW 1536   // 3*H : i, f, u x-side preactivations
#define NBLK 128
#define NTHR 512

// ---- device scratch (no allocation allowed) --------------------------------
__device__ float g_Gx  [(size_t)Bz * Sz * GXW];
__device__ float g_allH[(size_t)Bz * Sz * Hz];
__device__ float g_allC[(size_t)Bz * Sz * Hz];
__device__ float g_WfhH[(size_t)Bz * Sz * Hz];    // cache: Wfh @ allH[b,s]
__device__ float g_hsum[Bz * Hz];
__device__ float g_hprev[Bz * Hz];
__device__ float g_y[Bz * 4 * Hz];                // [b][{yi,yo,yu,y4}][h]
__device__ unsigned int g_bar_count;
__device__ unsigned int g_bar_gen;

// ---- f32x2 packed FMA helpers ----------------------------------------------
static __device__ __forceinline__ unsigned long long pk2(float x, float y) {
    unsigned long long r;
    asm("mov.b64 %0, {%1, %2};" : "=l"(r) : "f"(x), "f"(y));
    return r;
}
static __device__ __forceinline__ unsigned long long fma2(unsigned long long a,
                                                          unsigned long long b,
                                                          unsigned long long c) {
    unsigned long long d;
    asm("fma.rn.f32x2 %0, %1, %2, %3;" : "=l"(d) : "l"(a), "l"(b), "l"(c));
    return d;
}
static __device__ __forceinline__ float2 upk2(unsigned long long v) {
    float lo, hi;
    asm("mov.b64 {%0, %1}, %2;" : "=f"(lo), "=f"(hi) : "l"(v));
    return make_float2(lo, hi);
}
static __device__ __forceinline__ float sigm(float z) {
    return 1.0f / (1.0f + expf(-z));
}
static __device__ __forceinline__ float ldcg1(const float* p) {
    float v;
    asm volatile("ld.global.cg.f32 %0, [%1];" : "=f"(v) : "l"(p));
    return v;
}

// ---- P0: zero recurrent state + barrier vars -------------------------------
__global__ void k_init() {
    const size_t n = (size_t)Bz * Sz * Hz;
    const size_t stride = (size_t)gridDim.x * blockDim.x;
    size_t i = (size_t)blockIdx.x * blockDim.x + threadIdx.x;
    for (size_t j = i; j < n; j += stride) {
        g_allH[j] = 0.f; g_allC[j] = 0.f; g_WfhH[j] = 0.f;
    }
    for (size_t j = i; j < (size_t)Bz * Hz; j += stride) {
        g_hsum[j] = 0.f; g_hprev[j] = 0.f;
    }
    if (i == 0) { g_bar_count = 0u; g_bar_gen = 0u; }
}

// ---- P1: Gx = embed[x] @ {Wix,Wfx,Wux}^T + bias (known-good) ---------------
__global__ __launch_bounds__(256) void k_precompute(
    const int* __restrict__ x, const float* __restrict__ embed,
    const float* __restrict__ Wix, const float* __restrict__ bix,
    const float* __restrict__ Wfx, const float* __restrict__ bfx,
    const float* __restrict__ Wux, const float* __restrict__ bux)
{
    const int nt = blockIdx.x;            // 0..23
    const int mt = blockIdx.y;            // 0..127
    const int g  = nt >> 3;
    const int jbase = (nt & 7) * 64;
    const float* W    = (g == 0) ? Wix : (g == 1) ? Wfx : Wux;
    const float* bias = (g == 0) ? bix : (g == 1) ? bfx : bux;
    const int tid = threadIdx.x;

    __shared__ int wid[64];
    __shared__ __align__(16) float As[16][64];
    __shared__ __align__(16) float Bs[16][64];

    const int rowbase = mt * 64;
    if (tid < 64) wid[tid] = x[rowbase + tid];
    __syncthreads();

    const int sm  = tid >> 2;
    const int skq = tid & 3;
    const int tm  = tid >> 4;
    const int tn  = tid & 15;

    unsigned long long acc[4][2];
#pragma unroll
    for (int r = 0; r < 4; r++) { acc[r][0] = 0ull; acc[r][1] = 0ull; }

    for (int kc = 0; kc < 19; kc++) {
        const int k = kc * 16 + skq * 4;
        float4 va = make_float4(0.f,0.f,0.f,0.f), vb = va;
        if (k < Ez) {
            va = *reinterpret_cast<const float4*>(&embed[(size_t)wid[sm] * Ez + k]);
            vb = *reinterpret_cast<const float4*>(&W[(size_t)(jbase + sm) * Ez + k]);
        }
        As[skq*4+0][sm]=va.x; As[skq*4+1][sm]=va.y; As[skq*4+2][sm]=va.z; As[skq*4+3][sm]=va.w;
        Bs[skq*4+0][sm]=vb.x; Bs[skq*4+1][sm]=vb.y; Bs[skq*4+2][sm]=vb.z; Bs[skq*4+3][sm]=vb.w;
        __syncthreads();
#pragma unroll
        for (int kk = 0; kk < 16; kk++) {
            const float4 a4 = *reinterpret_cast<const float4*>(&As[kk][tm * 4]);
            const ulonglong2 bv = *reinterpret_cast<const ulonglong2*>(&Bs[kk][tn * 4]);
            const unsigned long long a0 = pk2(a4.x, a4.x);
            const unsigned long long a1 = pk2(a4.y, a4.y);
            const unsigned long long a2 = pk2(a4.z, a4.z);
            const unsigned long long a3 = pk2(a4.w, a4.w);
            acc[0][0]=fma2(a0,bv.x,acc[0][0]); acc[0][1]=fma2(a0,bv.y,acc[0][1]);
            acc[1][0]=fma2(a1,bv.x,acc[1][0]); acc[1][1]=fma2(a1,bv.y,acc[1][1]);
            acc[2][0]=fma2(a2,bv.x,acc[2][0]); acc[2][1]=fma2(a2,bv.y,acc[2][1]);
            acc[3][0]=fma2(a3,bv.x,acc[3][0]); acc[3][1]=fma2(a3,bv.y,acc[3][1]);
        }
        __syncthreads();
    }

    const int j = jbase + tn * 4;
#pragma unroll
    for (int r = 0; r < 4; r++) {
        const int row = rowbase + tm * 4 + r;
        float* dst = &g_Gx[(size_t)row * GXW + g * Hz + j];
        const float2 p0 = upk2(acc[r][0]);
        const float2 p1 = upk2(acc[r][1]);
        dst[0] = p0.x + bias[j+0]; dst[1] = p0.y + bias[j+1];
        dst[2] = p1.x + bias[j+2]; dst[3] = p1.y + bias[j+3];
    }
}

// ---- grid-wide sense barrier (R9-proven, verbatim) -------------------------
static __device__ __forceinline__ void gridbar(unsigned int& gen) {
    __syncthreads();
    if (threadIdx.x == 0) {
        __threadfence();
        unsigned int a = atomicAdd(&g_bar_count, 1u);
        if (a == NBLK - 1) {
            g_bar_count = 0u;
            __threadfence();
            atomicExch(&g_bar_gen, gen + 1u);
        } else {
            while (atomicAdd(&g_bar_gen, 0u) <= gen) { }
        }
        __threadfence();
    }
    gen++;
    __syncthreads();
}

// ---- persistent recurrence kernel ------------------------------------------
// smem: Wp 512x32 u64 (128KB) | As 2x64x64 f (32KB) | lists (8KB) | small
#define SM_WP    0
#define SM_AS    131072
#define SM_L0    163840            // short[64*64] = 8KB
#define SM_CNT   172032            // int[64]
#define SM_BFS   172288            // int[64]
#define SM_PM    172544            // u64[64]
#define SMEM_TOTAL 173568

extern __shared__ unsigned char smem_raw[];

__global__ __launch_bounds__(NTHR, 1) void k_recur(
    const int* __restrict__ bfs, const int* __restrict__ children,
    const float* __restrict__ Wih, const float* __restrict__ Wfh,
    const float* __restrict__ Wuh,
    const float* __restrict__ bih, const float* __restrict__ bfh,
    const float* __restrict__ buh,
    const float* __restrict__ Wout, const float* __restrict__ bout,
    float* __restrict__ out)
{
    const int blk = blockIdx.x;
    const int tid = threadIdx.x;

    unsigned long long* Wp = (unsigned long long*)(smem_raw + SM_WP);
    float* As   = (float*)(smem_raw + SM_AS);
    short* s_l0 = (short*)(smem_raw + SM_L0);
    int*   s_cnt = (int*)(smem_raw + SM_CNT);
    int*   s_bfs = (int*)(smem_raw + SM_BFS);
    unsigned long long* s_pm = (unsigned long long*)(smem_raw + SM_PM);

    // GEMM tile assignment (R9 verbatim)
    const int mt = blk >> 6;             // rows [mt*64, +64)  (batches)
    const int nt = blk & 63;             // cols [nt*32, +32)
    const int colbase = nt * 32;
    const int g = colbase >> 9;          // gate 0..3
    const int wrow0 = colbase & 511;
    const float* Wsrc = (g == 0) ? Wih : (g == 2) ? Wuh : Wfh;
    const int m0row = mt * 64;

    // one-time: W tile into smem as (w,w) pairs
    for (int i = tid; i < 32 * 512; i += NTHR) {
        const int c = i & 31, k = i >> 5;
        const float w = Wsrc[(size_t)(wrow0 + c) * Hz + k];
        Wp[(size_t)k * 32 + c] = pk2(w, w);
    }
    if (tid < Sz) s_bfs[tid] = bfs[blk * Sz + tid];
    const float vbih = bih[tid], vbfh = bfh[tid], vbuh = buh[tid];
    __syncthreads();

    // procmask prefix (serial, once)
    if (tid == 0) {
        unsigned long long pm = 0ull;
        for (int t = 0; t < Sz; t++) { s_pm[t] = pm; pm |= 1ull << s_bfs[t]; }
    }
    __syncthreads();

    const int wz = tid >> 5, lane = tid & 31;

    // build per-step child lists via ballot compaction (once)
    for (int q = 0; q < 4; q++) {
        const int t = wz + q * 16;
        const int cu = s_bfs[t];
        const unsigned long long pm = s_pm[t];
        const int* chrow = &children[((size_t)blk * Sz + cu) * Sz];
        const int s0 = lane, s1 = lane + 32;
        const bool p0 = (chrow[s0] != 0) && ((pm >> s0) & 1ull);
        const bool p1 = (chrow[s1] != 0) && ((pm >> s1) & 1ull);
        const unsigned b0 = __ballot_sync(0xffffffffu, p0);
        const unsigned b1 = __ballot_sync(0xffffffffu, p1);
        const unsigned mlt = (1u << lane) - 1u;
        if (p0) s_l0[t * 64 + __popc(b0 & mlt)] = (short)s0;
        if (p1) s_l0[t * 64 + __popc(b0) + __popc(b1 & mlt)] = (short)s1;
        if (lane == 0) s_cnt[t] = __popc(b0) + __popc(b1);
    }
    __syncthreads();

    // compute-warp geometry (warps 0..3, R9 verbatim): thread = 4 rows x 4 cols
    const int wr = (wz >> 1) & 1, wc = wz & 1;
    const int lr = lane >> 2,     lc = lane & 3;
    const int rloc = wr * 32 + lr * 4;               // row in [0,64)
    const int cloc = wc * 16 + lc * 4;               // col in [0,32)
    const int h = tid;
    const size_t bh = (size_t)blk * Sz * Hz + h;

    unsigned int gen = 0;

    for (int t = 0; t < Sz; t++) {
        // ===================== GEMM phase (R9 verbatim) =====================
        const float* Asrc = (g == 3) ? g_hprev : g_hsum;

        for (int i = tid; i < 1024; i += NTHR) {      // stage chunk 0
            const int row = i >> 4, kq = i & 15;
            const float4 v = *reinterpret_cast<const float4*>(
                &Asrc[(size_t)(m0row + row) * Hz + kq * 4]);
            const int rS = row ^ (kq << 2);
            float* d = &As[(kq * 4) * 64 + rS];
            d[0] = v.x; d[64] = v.y; d[128] = v.z; d[192] = v.w;
        }
        __syncthreads();

        unsigned long long acc[2][4];
#pragma unroll
        for (int c = 0; c < 4; c++) { acc[0][c] = 0ull; acc[1][c] = 0ull; }

        for (int kc = 0; kc < 8; kc++) {
            const int cb = kc & 1;
            if (wz >= 4) {                            // staging warps
                if (kc < 7) {
                    const int nb = (cb ^ 1) * 4096;
                    for (int i = tid - 128; i < 1024; i += 384) {
                        const int row = i >> 4, kq = i & 15;
                        const float4 v = *reinterpret_cast<const float4*>(
                            &Asrc[(size_t)(m0row + row) * Hz + (kc + 1) * 64 + kq * 4]);
                        const int rS = row ^ (kq << 2);
                        float* d = &As[nb + (kq * 4) * 64 + rS];
                        d[0] = v.x; d[64] = v.y; d[128] = v.z; d[192] = v.w;
                    }
                }
            } else {                                  // compute warps
                const float* Ab = &As[cb * 4096];
                const unsigned long long* Wb = &Wp[(size_t)(kc * 64) * 32];
#pragma unroll 16
                for (int kk = 0; kk < 64; kk++) {
                    const int v = ((kk >> 2) & 15) << 2;
                    const ulonglong2 ar = *reinterpret_cast<const ulonglong2*>(
                        &Ab[kk * 64 + (rloc ^ v)]);
                    const ulonglong2 w01 = *reinterpret_cast<const ulonglong2*>(
                        &Wb[kk * 32 + cloc]);
                    const ulonglong2 w23 = *reinterpret_cast<const ulonglong2*>(
                        &Wb[kk * 32 + cloc + 2]);
                    acc[0][0] = fma2(ar.x, w01.x, acc[0][0]);
                    acc[1][0] = fma2(ar.y, w01.x, acc[1][0]);
                    acc[0][1] = fma2(ar.x, w01.y, acc[0][1]);
                    acc[1][1] = fma2(ar.y, w01.y, acc[1][1]);
                    acc[0][2] = fma2(ar.x, w23.x, acc[0][2]);
                    acc[1][2] = fma2(ar.y, w23.x, acc[1][2]);
                    acc[0][3] = fma2(ar.x, w23.y, acc[0][3]);
                    acc[1][3] = fma2(ar.y, w23.y, acc[1][3]);
                }
            }
            __syncthreads();
        }

        if (wz < 4) {                                 // epilogue (R9 verbatim)
            const int grow = m0row + rloc;
            const int gcol = colbase + cloc;
#pragma unroll
            for (int c = 0; c < 4; c++) {
                const float2 p0 = upk2(acc[0][c]);
                const float2 p1 = upk2(acc[1][c]);
                g_y[(size_t)(grow + 0) * 2048 + gcol + c] = p0.x;
                g_y[(size_t)(grow + 1) * 2048 + gcol + c] = p0.y;
                g_y[(size_t)(grow + 2) * 2048 + gcol + c] = p1.x;
                g_y[(size_t)(grow + 3) * 2048 + gcol + c] = p1.y;
            }
        }
        __threadfence();

        // ============ batch-local gathers (pre-barrier overlap) ============
        const int cu = s_bfs[t];
        const int pv = (t > 0)      ? s_bfs[t - 1] : -1;
        const int nx = (t < Sz - 1) ? s_bfs[t + 1] : -1;
        const int n0 = s_cnt[t];
        const int n1 = (t < Sz - 1) ? s_cnt[t + 1] : 0;
        const short* L0 = &s_l0[t * 64];
        const short* L1 = &s_l0[(t + 1) * 64];

        const float* gx = &g_Gx[(size_t)(blk * Sz + cu) * GXW];
        const float gxi = gx[h], gxf = gx[Hz + h], gxu = gx[2 * Hz + h];
        const float base = gxf + vbfh;
        const float Cprev = (pv >= 0) ? g_allC[bh + (size_t)pv * Hz] : 0.f;

        float fc = 0.f, hs = 0.f;
        int fcPrev = 0, hsCur = 0;
        const int nm = (n0 > n1) ? n0 : n1;
#pragma unroll 2
        for (int i = 0; i < nm; i++) {
            if (i < n0) {
                const int s = L0[i];
                if (s != pv)
                    fc += sigm(g_WfhH[bh + (size_t)s * Hz] + base) *
                          g_allC[bh + (size_t)s * Hz];
                else fcPrev = 1;
            }
            if (i < n1) {
                const int s = L1[i];
                if (s != cu) hs += g_allH[bh + (size_t)s * Hz];
                else hsCur = 1;
            }
        }

        gridbar(gen);   // barrier A: all y tiles visible

        // ============ post-barrier finish (tiny) ============
        const float* yb = &g_y[(size_t)blk * 2048];
        const float yi = ldcg1(yb + h);
        const float yo = ldcg1(yb + Hz + h);
        const float yu = ldcg1(yb + 2 * Hz + h);
        const float y4 = ldcg1(yb + 3 * Hz + h);

        const float ig = sigm(gxi + yi + vbih);
        const float og = sigm(gxf + yo + vbfh);   // faithful: 'o' uses fx/fh
        const float ug = tanhf(gxu + yu + vbuh);
        if (fcPrev) fc += sigm(y4 + base) * Cprev;
        const float cc = ig * ug + fc;
        const float hn = og * tanhf(cc);
        if (hsCur) hs += hn;

        g_allC[bh + (size_t)cu * Hz] = cc;
        g_allH[bh + (size_t)cu * Hz] = hn;
        if (pv >= 0) g_WfhH[bh + (size_t)pv * Hz] = y4;
        g_hprev[blk * Hz + h] = hn;
        if (nx >= 0) g_hsum[blk * Hz + h] = hs;
        __threadfence();

        gridbar(gen);   // barrier B: hsum/hprev visible for next GEMM
    }

    // ===================== output head =====================
    if (tid < 32 * Lz) {
        const int w = tid >> 5, ln = tid & 31;
        float p = 0.f;
        for (int hh = ln; hh < Hz; hh += 32)
            p += g_hprev[blk * Hz + hh] * Wout[w * Hz + hh];
#pragma unroll
        for (int o = 16; o; o >>= 1) p += __shfl_down_sync(0xffffffffu, p, o);
        if (ln == 0) out[blk * Lz + w] = p + bout[w];
    }
}

// ---- launch ----------------------------------------------------------------
extern "C" void kernel_launch(void* const* d_in, const int* in_sizes, int n_in,
                              void* d_out, int out_size) {
    const int*   x        = (const int*)d_in[0];
    const int*   bfs      = (const int*)d_in[1];
    const int*   children = (const int*)d_in[2];
    const float* embed    = (const float*)d_in[3];
    const float* Wix = (const float*)d_in[4],  *bix = (const float*)d_in[5];
    const float* Wih = (const float*)d_in[6],  *bih = (const float*)d_in[7];
    const float* Wfx = (const float*)d_in[8],  *bfx = (const float*)d_in[9];
    const float* Wfh = (const float*)d_in[10], *bfh = (const float*)d_in[11];
    const float* Wux = (const float*)d_in[12], *bux = (const float*)d_in[13];
    const float* Wuh = (const float*)d_in[14], *buh = (const float*)d_in[15];
    const float* Wout = (const float*)d_in[16], *bout = (const float*)d_in[17];
    float* out = (float*)d_out;

    static bool attr_set = false;
    if (!attr_set) {
        cudaFuncSetAttribute(k_recur, cudaFuncAttributeMaxDynamicSharedMemorySize,
                             SMEM_TOTAL);
        attr_set = true;
    }

    k_init<<<1024, 256>>>();
    k_precompute<<<dim3(24, 128), 256>>>(x, embed, Wix, bix, Wfx, bfx, Wux, bux);
    k_recur<<<NBLK, NTHR, SMEM_TOTAL>>>(bfs, children, Wih, Wfh, Wuh,
                                        bih, bfh, buh, Wout, bout, out);
}

// round 17
// speedup vs baseline: 1.1725x; 1.0017x over previous
#include <cuda_runtime.h>
#include <cstdint>

#define Bz 128
#define Sz 64
#define Ez 300
#define Hz 512
#define Lz 5
#define GXW 1536   // 3*H : i, f, u x-side preactivations
#define NBLK 128
#define NTHR 512

// ---- device scratch (no allocation allowed) --------------------------------
__device__ float g_Gx  [(size_t)Bz * Sz * GXW];
__device__ float g_allH[(size_t)Bz * Sz * Hz];
__device__ float g_allC[(size_t)Bz * Sz * Hz];
__device__ float g_WfhH[(size_t)Bz * Sz * Hz];    // cache: Wfh @ allH[b,s]
__device__ float g_hsum[Bz * Hz];
__device__ float g_hprev[Bz * Hz];
__device__ float g_y[Bz * 4 * Hz];                // [b][{yi,yo,yu,y4}][h]
__device__ unsigned int g_bar_count;
__device__ unsigned int g_bar_gen;

// ---- f32x2 packed FMA helpers ----------------------------------------------
static __device__ __forceinline__ unsigned long long pk2(float x, float y) {
    unsigned long long r;
    asm("mov.b64 %0, {%1, %2};" : "=l"(r) : "f"(x), "f"(y));
    return r;
}
static __device__ __forceinline__ unsigned long long fma2(unsigned long long a,
                                                          unsigned long long b,
                                                          unsigned long long c) {
    unsigned long long d;
    asm("fma.rn.f32x2 %0, %1, %2, %3;" : "=l"(d) : "l"(a), "l"(b), "l"(c));
    return d;
}
static __device__ __forceinline__ float2 upk2(unsigned long long v) {
    float lo, hi;
    asm("mov.b64 {%0, %1}, %2;" : "=f"(lo), "=f"(hi) : "l"(v));
    return make_float2(lo, hi);
}
static __device__ __forceinline__ float sigm(float z) {
    return 1.0f / (1.0f + expf(-z));
}
static __device__ __forceinline__ float ldcg1(const float* p) {
    float v;
    asm volatile("ld.global.cg.f32 %0, [%1];" : "=f"(v) : "l"(p));
    return v;
}
static __device__ __forceinline__ unsigned int ldacq(const unsigned int* p) {
    unsigned int v;
    asm volatile("ld.acquire.gpu.u32 %0, [%1];" : "=r"(v) : "l"(p));
    return v;
}
static __device__ __forceinline__ void strel(unsigned int* p, unsigned int v) {
    asm volatile("st.release.gpu.u32 [%0], %1;" :: "l"(p), "r"(v) : "memory");
}

// ---- P0: zero recurrent state + barrier vars -------------------------------
__global__ void k_init() {
    const size_t n = (size_t)Bz * Sz * Hz;
    const size_t stride = (size_t)gridDim.x * blockDim.x;
    size_t i = (size_t)blockIdx.x * blockDim.x + threadIdx.x;
    for (size_t j = i; j < n; j += stride) {
        g_allH[j] = 0.f; g_allC[j] = 0.f; g_WfhH[j] = 0.f;
    }
    for (size_t j = i; j < (size_t)Bz * Hz; j += stride) {
        g_hsum[j] = 0.f; g_hprev[j] = 0.f;
    }
    if (i == 0) { g_bar_count = 0u; g_bar_gen = 0u; }
}

// ---- P1: Gx = embed[x] @ {Wix,Wfx,Wux}^T + bias (known-good) ---------------
__global__ __launch_bounds__(256) void k_precompute(
    const int* __restrict__ x, const float* __restrict__ embed,
    const float* __restrict__ Wix, const float* __restrict__ bix,
    const float* __restrict__ Wfx, const float* __restrict__ bfx,
    const float* __restrict__ Wux, const float* __restrict__ bux)
{
    const int nt = blockIdx.x;            // 0..23
    const int mt = blockIdx.y;            // 0..127
    const int g  = nt >> 3;
    const int jbase = (nt & 7) * 64;
    const float* W    = (g == 0) ? Wix : (g == 1) ? Wfx : Wux;
    const float* bias = (g == 0) ? bix : (g == 1) ? bfx : bux;
    const int tid = threadIdx.x;

    __shared__ int wid[64];
    __shared__ __align__(16) float As[16][64];
    __shared__ __align__(16) float Bs[16][64];

    const int rowbase = mt * 64;
    if (tid < 64) wid[tid] = x[rowbase + tid];
    __syncthreads();

    const int sm  = tid >> 2;
    const int skq = tid & 3;
    const int tm  = tid >> 4;
    const int tn  = tid & 15;

    unsigned long long acc[4][2];
#pragma unroll
    for (int r = 0; r < 4; r++) { acc[r][0] = 0ull; acc[r][1] = 0ull; }

    for (int kc = 0; kc < 19; kc++) {
        const int k = kc * 16 + skq * 4;
        float4 va = make_float4(0.f,0.f,0.f,0.f), vb = va;
        if (k < Ez) {
            va = *reinterpret_cast<const float4*>(&embed[(size_t)wid[sm] * Ez + k]);
            vb = *reinterpret_cast<const float4*>(&W[(size_t)(jbase + sm) * Ez + k]);
        }
        As[skq*4+0][sm]=va.x; As[skq*4+1][sm]=va.y; As[skq*4+2][sm]=va.z; As[skq*4+3][sm]=va.w;
        Bs[skq*4+0][sm]=vb.x; Bs[skq*4+1][sm]=vb.y; Bs[skq*4+2][sm]=vb.z; Bs[skq*4+3][sm]=vb.w;
        __syncthreads();
#pragma unroll
        for (int kk = 0; kk < 16; kk++) {
            const float4 a4 = *reinterpret_cast<const float4*>(&As[kk][tm * 4]);
            const ulonglong2 bv = *reinterpret_cast<const ulonglong2*>(&Bs[kk][tn * 4]);
            const unsigned long long a0 = pk2(a4.x, a4.x);
            const unsigned long long a1 = pk2(a4.y, a4.y);
            const unsigned long long a2 = pk2(a4.z, a4.z);
            const unsigned long long a3 = pk2(a4.w, a4.w);
            acc[0][0]=fma2(a0,bv.x,acc[0][0]); acc[0][1]=fma2(a0,bv.y,acc[0][1]);
            acc[1][0]=fma2(a1,bv.x,acc[1][0]); acc[1][1]=fma2(a1,bv.y,acc[1][1]);
            acc[2][0]=fma2(a2,bv.x,acc[2][0]); acc[2][1]=fma2(a2,bv.y,acc[2][1]);
            acc[3][0]=fma2(a3,bv.x,acc[3][0]); acc[3][1]=fma2(a3,bv.y,acc[3][1]);
        }
        __syncthreads();
    }

    const int j = jbase + tn * 4;
#pragma unroll
    for (int r = 0; r < 4; r++) {
        const int row = rowbase + tm * 4 + r;
        float* dst = &g_Gx[(size_t)row * GXW + g * Hz + j];
        const float2 p0 = upk2(acc[r][0]);
        const float2 p1 = upk2(acc[r][1]);
        dst[0] = p0.x + bias[j+0]; dst[1] = p0.y + bias[j+1];
        dst[2] = p1.x + bias[j+2]; dst[3] = p1.y + bias[j+3];
    }
}

// ---- grid-wide barrier: atomic arrival, LOAD-based poll (no RMW spam) ------
static __device__ __forceinline__ void gridbar(unsigned int& gen) {
    __syncthreads();
    if (threadIdx.x == 0) {
        __threadfence();
        unsigned int a = atomicAdd(&g_bar_count, 1u);
        if (a == NBLK - 1) {
            g_bar_count = 0u;
            __threadfence();
            strel(&g_bar_gen, gen + 1u);
        } else {
            while (ldacq(&g_bar_gen) <= gen) { }
        }
        __threadfence();
    }
    gen++;
    __syncthreads();
}

// ---- persistent recurrence kernel ------------------------------------------
// smem: Wp 512x32 u64 (128KB) | As 2x64x64 f (32KB) | lists (8KB) | small
#define SM_WP    0
#define SM_AS    131072
#define SM_L0    163840            // short[64*64] = 8KB
#define SM_CNT   172032            // int[64]
#define SM_BFS   172288            // int[64]
#define SM_PM    172544            // u64[64]
#define SMEM_TOTAL 173568

extern __shared__ unsigned char smem_raw[];

__global__ __launch_bounds__(NTHR, 1) void k_recur(
    const int* __restrict__ bfs, const int* __restrict__ children,
    const float* __restrict__ Wih, const float* __restrict__ Wfh,
    const float* __restrict__ Wuh,
    const float* __restrict__ bih, const float* __restrict__ bfh,
    const float* __restrict__ buh,
    const float* __restrict__ Wout, const float* __restrict__ bout,
    float* __restrict__ out)
{
    const int blk = blockIdx.x;
    const int tid = threadIdx.x;

    unsigned long long* Wp = (unsigned long long*)(smem_raw + SM_WP);
    float* As   = (float*)(smem_raw + SM_AS);
    short* s_l0 = (short*)(smem_raw + SM_L0);
    int*   s_cnt = (int*)(smem_raw + SM_CNT);
    int*   s_bfs = (int*)(smem_raw + SM_BFS);
    unsigned long long* s_pm = (unsigned long long*)(smem_raw + SM_PM);

    // GEMM tile assignment
    const int mt = blk >> 6;             // rows [mt*64, +64)  (batches)
    const int nt = blk & 63;             // cols [nt*32, +32)
    const int colbase = nt * 32;
    const int g = colbase >> 9;          // gate 0..3
    const int wrow0 = colbase & 511;
    const float* Wsrc = (g == 0) ? Wih : (g == 2) ? Wuh : Wfh;
    const int m0row = mt * 64;

    // one-time: W tile into smem as (w,w) pairs
    for (int i = tid; i < 32 * 512; i += NTHR) {
        const int c = i & 31, k = i >> 5;
        const float w = Wsrc[(size_t)(wrow0 + c) * Hz + k];
        Wp[(size_t)k * 32 + c] = pk2(w, w);
    }
    if (tid < Sz) s_bfs[tid] = bfs[blk * Sz + tid];
    const float vbih = bih[tid], vbfh = bfh[tid], vbuh = buh[tid];
    __syncthreads();

    // procmask prefix (serial, once)
    if (tid == 0) {
        unsigned long long pm = 0ull;
        for (int t = 0; t < Sz; t++) { s_pm[t] = pm; pm |= 1ull << s_bfs[t]; }
    }
    __syncthreads();

    const int wz = tid >> 5, lane = tid & 31;

    // build per-step child lists via ballot compaction (once)
    for (int q = 0; q < 4; q++) {
        const int t = wz + q * 16;
        const int cu = s_bfs[t];
        const unsigned long long pm = s_pm[t];
        const int* chrow = &children[((size_t)blk * Sz + cu) * Sz];
        const int s0 = lane, s1 = lane + 32;
        const bool p0 = (chrow[s0] != 0) && ((pm >> s0) & 1ull);
        const bool p1 = (chrow[s1] != 0) && ((pm >> s1) & 1ull);
        const unsigned b0 = __ballot_sync(0xffffffffu, p0);
        const unsigned b1 = __ballot_sync(0xffffffffu, p1);
        const unsigned mlt = (1u << lane) - 1u;
        if (p0) s_l0[t * 64 + __popc(b0 & mlt)] = (short)s0;
        if (p1) s_l0[t * 64 + __popc(b0) + __popc(b1 & mlt)] = (short)s1;
        if (lane == 0) s_cnt[t] = __popc(b0) + __popc(b1);
    }
    __syncthreads();

    // compute-warp geometry (warps 0..3): thread = 4 rows x 4 cols
    const int wr = (wz >> 1) & 1, wc = wz & 1;
    const int lr = lane >> 2,     lc = lane & 3;
    const int rloc = wr * 32 + lr * 4;               // row in [0,64)
    const int cloc = wc * 16 + lc * 4;               // col in [0,32)
    const int h = tid;
    const size_t bh = (size_t)blk * Sz * Hz + h;

    unsigned int gen = 0;

    for (int t = 0; t < Sz; t++) {
        // ===================== GEMM phase =====================
        const float* Asrc = (g == 3) ? g_hprev : g_hsum;

        for (int i = tid; i < 1024; i += NTHR) {      // stage chunk 0
            const int row = i >> 4, kq = i & 15;
            const float4 v = *reinterpret_cast<const float4*>(
                &Asrc[(size_t)(m0row + row) * Hz + kq * 4]);
            const int rS = row ^ (kq << 2);
            float* d = &As[(kq * 4) * 64 + rS];
            d[0] = v.x; d[64] = v.y; d[128] = v.z; d[192] = v.w;
        }
        __syncthreads();

        unsigned long long acc[2][4];
#pragma unroll
        for (int c = 0; c < 4; c++) { acc[0][c] = 0ull; acc[1][c] = 0ull; }

        for (int kc = 0; kc < 8; kc++) {
            const int cb = kc & 1;
            if (wz >= 4) {                            // staging warps
                if (kc < 7) {
                    const int nb = (cb ^ 1) * 4096;
                    for (int i = tid - 128; i < 1024; i += 384) {
                        const int row = i >> 4, kq = i & 15;
                        const float4 v = *reinterpret_cast<const float4*>(
                            &Asrc[(size_t)(m0row + row) * Hz + (kc + 1) * 64 + kq * 4]);
                        const int rS = row ^ (kq << 2);
                        float* d = &As[nb + (kq * 4) * 64 + rS];
                        d[0] = v.x; d[64] = v.y; d[128] = v.z; d[192] = v.w;
                    }
                }
            } else {                                  // compute warps
                const float* Ab = &As[cb * 4096];
                const unsigned long long* Wb = &Wp[(size_t)(kc * 64) * 32];
#pragma unroll 16
                for (int kk = 0; kk < 64; kk++) {
                    const int v = ((kk >> 2) & 15) << 2;
                    const ulonglong2 ar = *reinterpret_cast<const ulonglong2*>(
                        &Ab[kk * 64 + (rloc ^ v)]);
                    const ulonglong2 w01 = *reinterpret_cast<const ulonglong2*>(
                        &Wb[kk * 32 + cloc]);
                    const ulonglong2 w23 = *reinterpret_cast<const ulonglong2*>(
                        &Wb[kk * 32 + cloc + 2]);
                    acc[0][0] = fma2(ar.x, w01.x, acc[0][0]);
                    acc[1][0] = fma2(ar.y, w01.x, acc[1][0]);
                    acc[0][1] = fma2(ar.x, w01.y, acc[0][1]);
                    acc[1][1] = fma2(ar.y, w01.y, acc[1][1]);
                    acc[0][2] = fma2(ar.x, w23.x, acc[0][2]);
                    acc[1][2] = fma2(ar.y, w23.x, acc[1][2]);
                    acc[0][3] = fma2(ar.x, w23.y, acc[0][3]);
                    acc[1][3] = fma2(ar.y, w23.y, acc[1][3]);
                }
            }
            __syncthreads();
        }

        if (wz < 4) {                                 // epilogue
            const int grow = m0row + rloc;
            const int gcol = colbase + cloc;
#pragma unroll
            for (int c = 0; c < 4; c++) {
                const float2 p0 = upk2(acc[0][c]);
                const float2 p1 = upk2(acc[1][c]);
                g_y[(size_t)(grow + 0) * 2048 + gcol + c] = p0.x;
                g_y[(size_t)(grow + 1) * 2048 + gcol + c] = p0.y;
                g_y[(size_t)(grow + 2) * 2048 + gcol + c] = p1.x;
                g_y[(size_t)(grow + 3) * 2048 + gcol + c] = p1.y;
            }
        }
        __threadfence();

        // ============ batch-local gathers ============
        const int cu = s_bfs[t];
        const int pv = (t > 0)      ? s_bfs[t - 1] : -1;
        const int nx = (t < Sz - 1) ? s_bfs[t + 1] : -1;
        const int n0 = s_cnt[t];
        const int n1 = (t < Sz - 1) ? s_cnt[t + 1] : 0;
        const short* L0 = &s_l0[t * 64];
        const short* L1 = &s_l0[(t + 1) * 64];

        const float* gx = &g_Gx[(size_t)(blk * Sz + cu) * GXW];
        const float gxi = gx[h], gxf = gx[Hz + h], gxu = gx[2 * Hz + h];
        const float base = gxf + vbfh;
        const float Cprev = (pv >= 0) ? g_allC[bh + (size_t)pv * Hz] : 0.f;

        float fc = 0.f, hs = 0.f;
        int fcPrev = 0, hsCur = 0;
        const int nm = (n0 > n1) ? n0 : n1;
#pragma unroll 2
        for (int i = 0; i < nm; i++) {
            if (i < n0) {
                const int s = L0[i];
                if (s != pv)
                    fc += sigm(g_WfhH[bh + (size_t)s * Hz] + base) *
                          g_allC[bh + (size_t)s * Hz];
                else fcPrev = 1;
            }
            if (i < n1) {
                const int s = L1[i];
                if (s != cu) hs += g_allH[bh + (size_t)s * Hz];
                else hsCur = 1;
            }
        }

        gridbar(gen);   // barrier A: all y tiles visible

        // ============ post-barrier finish (tiny) ============
        const float* yb = &g_y[(size_t)blk * 2048];
        const float yi = ldcg1(yb + h);
        const float yo = ldcg1(yb + Hz + h);
        const float yu = ldcg1(yb + 2 * Hz + h);
        const float y4 = ldcg1(yb + 3 * Hz + h);

        const float ig = sigm(gxi + yi + vbih);
        const float og = sigm(gxf + yo + vbfh);   // faithful: 'o' uses fx/fh
        const float ug = tanhf(gxu + yu + vbuh);
        if (fcPrev) fc += sigm(y4 + base) * Cprev;
        const float cc = ig * ug + fc;
        const float hn = og * tanhf(cc);
        if (hsCur) hs += hn;

        g_allC[bh + (size_t)cu * Hz] = cc;
        g_allH[bh + (size_t)cu * Hz] = hn;
        if (pv >= 0) g_WfhH[bh + (size_t)pv * Hz] = y4;
        g_hprev[blk * Hz + h] = hn;
        if (nx >= 0) g_hsum[blk * Hz + h] = hs;
        __threadfence();

        gridbar(gen);   // barrier B: hsum/hprev visible for next GEMM
    }

    // ===================== output head =====================
    if (tid < 32 * Lz) {
        const int w = tid >> 5, ln = tid & 31;
        float p = 0.f;
        for (int hh = ln; hh < Hz; hh += 32)
            p += g_hprev[blk * Hz + hh] * Wout[w * Hz + hh];
#pragma unroll
        for (int o = 16; o; o >>= 1) p += __shfl_down_sync(0xffffffffu, p, o);
        if (ln == 0) out[blk * Lz + w] = p + bout[w];
    }
}

// ---- launch ----------------------------------------------------------------
extern "C" void kernel_launch(void* const* d_in, const int* in_sizes, int n_in,
                              void* d_out, int out_size) {
    const int*   x        = (const int*)d_in[0];
    const int*   bfs      = (const int*)d_in[1];
    const int*   children = (const int*)d_in[2];
    const float* embed    = (const float*)d_in[3];
    const float* Wix = (const float*)d_in[4],  *bix = (const float*)d_in[5];
    const float* Wih = (const float*)d_in[6],  *bih = (const float*)d_in[7];
    const float* Wfx = (const float*)d_in[8],  *bfx = (const float*)d_in[9];
    const float* Wfh = (const float*)d_in[10], *bfh = (const float*)d_in[11];
    const float* Wux = (const float*)d_in[12], *bux = (const float*)d_in[13];
    const float* Wuh = (const float*)d_in[14], *buh = (const float*)d_in[15];
    const float* Wout = (const float*)d_in[16], *bout = (const float*)d_in[17];
    float* out = (float*)d_out;

    static bool attr_set = false;
    if (!attr_set) {
        cudaFuncSetAttribute(k_recur, cudaFuncAttributeMaxDynamicSharedMemorySize,
                             SMEM_TOTAL);
        attr_set = true;
    }

    k_init<<<1024, 256>>>();
    k_precompute<<<dim3(24, 128), 256>>>(x, embed, Wix, bix, Wfx, bfx, Wux, bux);
    k_recur<<<NBLK, NTHR, SMEM_TOTAL>>>(bfs, children, Wih, Wfh, Wuh,
                                        bih, bfh, buh, Wout, bout, out);
}